// round 17
// baseline (speedup 1.0000x reference)
#include <cuda_runtime.h>
#include <cuda_bf16.h>

// Problem constants
#define B_SZ   512
#define IN_F   512
#define OUT_F  64
#define KD     16
#define NF     (OUT_F * KD)   // 1024
#define NBLK   544            // persistent grid (4/SM x 136 SMs worth; <= 592 resident)

typedef unsigned long long u64;
typedef unsigned int u32;

// Scratch: bf16 inputs, bf16 M [o][b][k/2], S accum, finalize counters, barrier
__device__ u32 g_xb[B_SZ * IN_F / 2];          // x as bf16x2, [m][k]
__device__ u32 g_Tb[NF * IN_F / 2];            // T^T as bf16x2, [n][k]
__device__ u32 g_Mb[OUT_F * B_SZ * KD / 2];    // M as bf16x2, [o][b][k/2]
__device__ float g_S[OUT_F * B_SZ];
__device__ unsigned int g_cnt[OUT_F * 16];     // per (o, 32-row group)
__device__ unsigned int g_bar_count;           // zero-init
__device__ volatile unsigned int g_bar_gen;    // monotonic across replays

// ---- packed helpers (sm_103a) ---------------------------------------------
__device__ __forceinline__ u32 hadd2b(u32 a, u32 b) {
    u32 r; asm("add.rn.bf16x2 %0, %1, %2;" : "=r"(r) : "r"(a), "r"(b)); return r;
}
__device__ __forceinline__ u32 habs2(u32 a) { return a & 0x7FFF7FFFu; }
__device__ __forceinline__ u32 cvt2(float lo, float hi) {
    u32 r; asm("cvt.rn.bf16x2.f32 %0, %1, %2;" : "=r"(r) : "f"(hi), "f"(lo)); return r;
}
__device__ __forceinline__ void mma_bf16(float& d0, float& d1, float& d2, float& d3,
                                         u32 a0, u32 a1, u32 a2, u32 a3,
                                         u32 b0, u32 b1) {
    asm volatile(
        "mma.sync.aligned.m16n8k16.row.col.f32.bf16.bf16.f32 "
        "{%0,%1,%2,%3}, {%4,%5,%6,%7}, {%8,%9}, {%0,%1,%2,%3};"
        : "+f"(d0), "+f"(d1), "+f"(d2), "+f"(d3)
        : "r"(a0), "r"(a1), "r"(a2), "r"(a3), "r"(b0), "r"(b1));
}

// Sense-reversal grid barrier (replay-safe: generation read at entry).
__device__ __forceinline__ void grid_barrier() {
    __syncthreads();
    if (threadIdx.x == 0) {
        __threadfence();
        unsigned int gen = g_bar_gen;
        if (atomicAdd(&g_bar_count, 1u) == NBLK - 1u) {
            atomicExch(&g_bar_count, 0u);
            __threadfence();
            g_bar_gen = gen + 1u;
        } else {
            while (g_bar_gen == gen) { }
        }
    }
    __syncthreads();
}

// ---- pairwise helpers ------------------------------------------------------
__device__ __constant__ unsigned char PAIR_A[136] = {
 0,0,0,0,0,0,0,0,0,0,0,0,0,0,0,
 1,1,1,1,1,1,1,1,1,1,1,1,1,1,
 2,2,2,2,2,2,2,2,2,2,2,2,2,
 3,3,3,3,3,3,3,3,3,3,3,3,
 4,4,4,4,4,4,4,4,4,4,4,
 5,5,5,5,5,5,5,5,5,5,
 6,6,6,6,6,6,6,6,6,
 7,7,7,7,7,7,7,7,
 8,8,8,8,8,8,8,
 9,9,9,9,9,9,
 10,10,10,10,10,
 11,11,11,11,
 12,12,12,
 13,13,
 14,
 0,1,2,3,4,5,6,7,8,9,10,11,12,13,14,15};
__device__ __constant__ unsigned char PAIR_B[136] = {
 1,2,3,4,5,6,7,8,9,10,11,12,13,14,15,
 2,3,4,5,6,7,8,9,10,11,12,13,14,15,
 3,4,5,6,7,8,9,10,11,12,13,14,15,
 4,5,6,7,8,9,10,11,12,13,14,15,
 5,6,7,8,9,10,11,12,13,14,15,
 6,7,8,9,10,11,12,13,14,15,
 7,8,9,10,11,12,13,14,15,
 8,9,10,11,12,13,14,15,
 9,10,11,12,13,14,15,
 10,11,12,13,14,15,
 11,12,13,14,15,
 12,13,14,15,
 13,14,15,
 14,15,
 15,
 0,1,2,3,4,5,6,7,8,9,10,11,12,13,14,15};

__device__ __forceinline__ float bterm(const uint4* __restrict__ s4,
                                       const u32* __restrict__ mjn, int i)
{
    uint4 va = s4[i * 2 + 0];
    uint4 vb = s4[i * 2 + 1];
    u32 d0 = habs2(hadd2b(va.x, mjn[0]));
    u32 d1 = habs2(hadd2b(va.y, mjn[1]));
    u32 d2 = habs2(hadd2b(va.z, mjn[2]));
    u32 d3 = habs2(hadd2b(va.w, mjn[3]));
    u32 d4 = habs2(hadd2b(vb.x, mjn[4]));
    u32 d5 = habs2(hadd2b(vb.y, mjn[5]));
    u32 d6 = habs2(hadd2b(vb.z, mjn[6]));
    u32 d7 = habs2(hadd2b(vb.w, mjn[7]));
    u32 t = hadd2b(hadd2b(hadd2b(d0, d1), hadd2b(d2, d3)),
                   hadd2b(hadd2b(d4, d5), hadd2b(d6, d7)));
    float lo = __uint_as_float(t << 16);
    float hi = __uint_as_float(t & 0xFFFF0000u);
    return __expf(-(lo + hi));
}

// ---------------------------------------------------------------------------
// Fused persistent kernel: prep -> barrier -> GEMM -> barrier -> pairwise.
// ---------------------------------------------------------------------------
#define GSTEP 8
#define RB 144

__global__ __launch_bounds__(256, 4) void mbd_fused_kernel(
    const float* __restrict__ x, const float* __restrict__ wv,
    const float* __restrict__ T, float* __restrict__ out)
{
    __shared__ union {
        float sT[16][68];                                  // prep: 4.3 KB
        struct { unsigned char A[2][64 * RB];
                 unsigned char B[2][64 * RB]; } g;         // gemm: 36.9 KB
        struct { u32 sM[B_SZ * 8];
                 float sR[8][32 * 32]; } p;                // pairwise: 48 KB
    } sm;

    const int tid = threadIdx.x;
    const int blk = blockIdx.x;

    // ===== Phase 1: prep (x->bf16, T->T^T bf16, zero g_S) =====
    {
        int gtid = blk * 256 + tid;
        if (gtid < 65536) {                                // x: 65536 float4
            float4 f = ((const float4*)x)[gtid];
            g_xb[gtid * 2 + 0] = cvt2(f.x, f.y);
            g_xb[gtid * 2 + 1] = cvt2(f.z, f.w);
        } else if (gtid < 65536 + 32768) {                 // g_S zero
            g_S[gtid - 65536] = 0.0f;
        }
        if (blk < 512) {                                   // T tile 16k x 64n
            int bx = blk & 15, by = blk >> 4;
            int k0 = by * 16, n0 = bx * 64;
            {
                int r = tid >> 4;
                int c = tid & 15;
                float4 v = ((const float4*)T)[(k0 + r) * (NF / 4) + (n0 / 4) + c];
                *(float4*)&sm.sT[r][c * 4] = v;
            }
            __syncthreads();
            {
                int nn = tid >> 2;
                int kb = tid & 3;
#pragma unroll
                for (int i = 0; i < 2; i++) {
                    int ki = kb * 2 + i;
                    u32 v = cvt2(sm.sT[ki * 2][nn], sm.sT[ki * 2 + 1][nn]);
                    g_Tb[(n0 + nn) * (IN_F / 2) + k0 / 2 + ki] = v;
                }
            }
        }
    }
    grid_barrier();

    // ===== Phase 2: HMMA GEMM (blocks 0..127; threads 0..127 active) =====
    if (blk < 128) {
        const bool act = (tid < 128);
        const int w  = tid >> 5;
        const int l  = tid & 31;
        const int g  = l >> 2;
        const int tg = l & 3;
        const int nt = blk & 15;
        const int mt = blk >> 4;
        const int m0 = mt * 64;
        const int n0 = nt * 64;

        const int sr = (tid & 127) >> 1;
        const int sc = (tid & 1) * 4;
        const uint4* xs4 = (const uint4*)g_xb;
        const uint4* Ts4 = (const uint4*)g_Tb;

        float d[8][4];
#pragma unroll
        for (int nc = 0; nc < 8; nc++)
#pragma unroll
            for (int i = 0; i < 4; i++) d[nc][i] = 0.f;

        if (act) {
#pragma unroll
            for (int i = 0; i < 4; i++) {
                uint4 va = xs4[(m0 + sr) * 64 + (sc + i)];
                uint4 vb = Ts4[(n0 + sr) * 64 + (sc + i)];
                *(uint4*)(sm.g.A[0] + sr * RB + (sc + i) * 16) = va;
                *(uint4*)(sm.g.B[0] + sr * RB + (sc + i) * 16) = vb;
            }
        }

        const int aoff = (w * 16 + g) * RB + tg * 4;

        int buf = 0;
#pragma unroll
        for (int s = 0; s < GSTEP; s++) {
            __syncthreads();

            uint4 pa[4], pb[4];
            if (act && s < GSTEP - 1) {
#pragma unroll
                for (int i = 0; i < 4; i++) {
                    pa[i] = xs4[(m0 + sr) * 64 + (s + 1) * 8 + (sc + i)];
                    pb[i] = Ts4[(n0 + sr) * 64 + (s + 1) * 8 + (sc + i)];
                }
            }

            if (act) {
                const unsigned char* A = sm.g.A[buf];
                const unsigned char* B = sm.g.B[buf];
#pragma unroll
                for (int kc = 0; kc < 4; kc++) {
                    u32 a0 = *(const u32*)(A + aoff + kc * 32);
                    u32 a1 = *(const u32*)(A + aoff + kc * 32 + 8 * RB);
                    u32 a2 = *(const u32*)(A + aoff + kc * 32 + 16);
                    u32 a3 = *(const u32*)(A + aoff + kc * 32 + 8 * RB + 16);
#pragma unroll
                    for (int nc = 0; nc < 8; nc++) {
                        const unsigned char* bp = B + (nc * 8 + g) * RB + tg * 4 + kc * 32;
                        u32 b0 = *(const u32*)bp;
                        u32 b1 = *(const u32*)(bp + 16);
                        mma_bf16(d[nc][0], d[nc][1], d[nc][2], d[nc][3],
                                 a0, a1, a2, a3, b0, b1);
                    }
                }
            }

            if (act && s < GSTEP - 1) {
                int b2 = buf ^ 1;
#pragma unroll
                for (int i = 0; i < 4; i++) {
                    *(uint4*)(sm.g.A[b2] + sr * RB + (sc + i) * 16) = pa[i];
                    *(uint4*)(sm.g.B[b2] + sr * RB + (sc + i) * 16) = pb[i];
                }
            }
            buf ^= 1;
        }

        if (act) {
            const int row0 = m0 + w * 16 + g;
#pragma unroll
            for (int nc = 0; nc < 8; nc++) {
                int col = n0 + nc * 8 + tg * 2;
                int o = col >> 4;
                int k = col & 15;
                g_Mb[(o * B_SZ + row0) * (KD / 2) + (k >> 1)]     = cvt2(d[nc][0], d[nc][1]);
                g_Mb[(o * B_SZ + row0 + 8) * (KD / 2) + (k >> 1)] = cvt2(d[nc][2], d[nc][3]);
            }
        }
    }
    grid_barrier();

    // ===== Phase 3: symmetric pairwise (2 units of 1088 per block) =====
    const int wd = tid >> 5;
    const int l  = tid & 31;

#pragma unroll 1
    for (int rep = 0; rep < 2; rep++) {
        __syncthreads();                       // prior rep's sM readers done
        const int u  = blk + rep * NBLK;       // 0..1087
        const int o  = u / 17;
        const int bp = u % 17;
        const int pr = bp * 8 + wd;            // pair 0..135
        const int ga = PAIR_A[pr];
        const int gb = PAIR_B[pr];
        const bool diag = (ga == gb);

        // Stage whole 512-row o-slice (1024 uint4, 4 per thread)
        {
            const uint4* src = ((const uint4*)g_Mb) + o * 1024;
            uint4* dst = (uint4*)sm.p.sM;
#pragma unroll
            for (int t = 0; t < 4; t++)
                dst[tid + t * 256] = src[tid + t * 256];
        }
        __syncthreads();

        u32 mjn[8];
#pragma unroll
        for (int p = 0; p < 8; p++)
            mjn[p] = sm.p.sM[(ga * 32 + l) * 8 + p] ^ 0x80008000u;

        const uint4* s4 = (const uint4*)sm.p.sM + gb * 64;

        if (diag) {
            float S0 = 0.f, S1 = 0.f, S2 = 0.f, S3 = 0.f;
#pragma unroll
            for (int s = 0; s < 32; s += 4) {
                S0 += bterm(s4, mjn, s + 0);
                S1 += bterm(s4, mjn, s + 1);
                S2 += bterm(s4, mjn, s + 2);
                S3 += bterm(s4, mjn, s + 3);
            }
            atomicAdd(&g_S[o * B_SZ + ga * 32 + l], (S0 + S1) + (S2 + S3));
        } else {
            float* myR = sm.p.sR[wd];
            float Sj = 0.f;
#pragma unroll
            for (int s = 0; s < 32; s++) {
                float term = bterm(s4, mjn, s);
                Sj += term;
                myR[l * 32 + ((s + l) & 31)] = term;    // banks (s+l)%32
            }
            __syncwarp();
            float A0 = 0.f, A1 = 0.f, A2 = 0.f, A3 = 0.f;
#pragma unroll
            for (int m = 0; m < 32; m += 4) {
                A0 += myR[(m + 0) * 32 + ((l + m + 0) & 31)];
                A1 += myR[(m + 1) * 32 + ((l + m + 1) & 31)];
                A2 += myR[(m + 2) * 32 + ((l + m + 2) & 31)];
                A3 += myR[(m + 3) * 32 + ((l + m + 3) & 31)];
            }
            float Si = (A0 + A1) + (A2 + A3);
            atomicAdd(&g_S[o * B_SZ + ga * 32 + l], Sj);
            atomicAdd(&g_S[o * B_SZ + gb * 32 + l], Si);
        }

        // Finalize: each group has exactly 16 contributing warps
        __threadfence();
        u32 doneA = 0, doneB = 0;
        if (l == 0) {
            doneA = (atomicAdd(&g_cnt[o * 16 + ga], 1u) == 15u);
            if (!diag)
                doneB = (atomicAdd(&g_cnt[o * 16 + gb], 1u) == 15u);
        }
        doneA = __shfl_sync(0xffffffffu, doneA, 0);
        doneB = __shfl_sync(0xffffffffu, doneB, 0);
        if (doneA) {
            __threadfence();
            int jj = ga * 32 + l;
            out[jj * OUT_F + o] = wv[jj] * (g_S[o * B_SZ + jj] - 1.0f);
            if (l == 0) g_cnt[o * 16 + ga] = 0u;
        }
        if (doneB) {
            __threadfence();
            int jj = gb * 32 + l;
            out[jj * OUT_F + o] = wv[jj] * (g_S[o * B_SZ + jj] - 1.0f);
            if (l == 0) g_cnt[o * 16 + gb] = 0u;
        }
    }
}

// ---------------------------------------------------------------------------
extern "C" void kernel_launch(void* const* d_in, const int* in_sizes, int n_in,
                              void* d_out, int out_size)
{
    const float* x = (const float*)d_in[0];   // [512, 512]
    const float* w = (const float*)d_in[1];   // [1, 512]
    const float* T = (const float*)d_in[2];   // [512, 64, 16]
    float* out = (float*)d_out;               // [512, 64]

    (void)in_sizes; (void)n_in; (void)out_size;

    mbd_fused_kernel<<<NBLK, 256>>>(x, w, T, out);
}